// round 9
// baseline (speedup 1.0000x reference)
#include <cuda_runtime.h>
#include <cstdint>

// Idx2PixelLayer: bilinear gather of N=1e6 points from a 2048x2048x8 fp32 image.
// c = ((coord - 1) mod (dim - 4)) + 1   (non-negative mod, JAX semantics)
// out = w00*g(0,0) + w10*g(1,0) + w01*g(0,1) + w11*g(1,1)
//   w00=d0*d1, w10=(1-d0)*d1, w01=d0*(1-d1), w11=(1-d0)*(1-d1)
// Reference's off-mask is always false (c <= 2045 < 2048), so dropped.
//
// R8: SPATIAL BINNING. R6 proved image DRAM collapses to compulsory traffic
// when the concurrent working set fits L2; R4/R7 proved cache-hint pinning
// does not achieve this. So make locality explicit: K1 bins point-ids by
// image row (16 bins x 128 rows = 8MB of image each) using block-aggregated
// histograms (few atomics); K2 processes bin-by-bin in bid order, so the
// ~1200 concurrent blocks only touch ~2-3 bins (~20MB) of image at a time ->
// in-launch L2 dedup + DRAM request locality. Processing keeps the proven
// 2-threads-per-point layout (lane pairs cover one 32B pixel sector/gather).

static constexpr int H = 2048;
static constexpr int W = 2048;
static constexpr int C = 8;

static constexpr int NBINS   = 16;
static constexpr int BIN_SHIFT = 7;        // i0 >> 7  (128 rows per bin)
static constexpr int CAP     = 65536;      // slots per bin (mean 62.5k, +12.5 sigma)

__device__ int g_bin_count[NBINS];
__device__ int g_ids[NBINS * CAP];

// ---- shared point math ----------------------------------------------------

struct PointCtx {
    int   i0, i1;
    float w00, w10, w01, w11;
};

__device__ __forceinline__ PointCtx make_ctx(float2 xy) {
    const float m0 = (float)(H - 4);   // 2044
    const float m1 = (float)(W - 4);

    float c0 = fmodf(xy.x - 1.0f, m0); if (c0 < 0.0f) c0 += m0; c0 += 1.0f;
    float c1 = fmodf(xy.y - 1.0f, m1); if (c1 < 0.0f) c1 += m1; c1 += 1.0f;

    float f0 = floorf(c0);
    float f1 = floorf(c1);
    float d0 = c0 - f0;
    float d1 = c1 - f1;

    PointCtx ctx;
    ctx.i0 = (int)f0;
    ctx.i1 = (int)f1;
    ctx.w00 = d0 * d1;
    ctx.w10 = (1.0f - d0) * d1;
    ctx.w01 = d0 * (1.0f - d1);
    ctx.w11 = (1.0f - d0) * (1.0f - d1);
    return ctx;
}

// Gather + blend channel half k (floats [4k, 4k+4)) of one point; store.
__device__ __forceinline__ void process_half(const PointCtx& c, int k,
                                             const float* __restrict__ visible,
                                             float* __restrict__ out, int p) {
    int base = (c.i0 * W + c.i1) * C + 4 * k;
    const float4* p00 = reinterpret_cast<const float4*>(visible + base);
    const float4* p01 = reinterpret_cast<const float4*>(visible + base + C);
    const float4* p10 = reinterpret_cast<const float4*>(visible + base + W * C);
    const float4* p11 = reinterpret_cast<const float4*>(visible + base + W * C + C);

    float4 a00 = __ldg(p00);
    float4 a01 = __ldg(p01);
    float4 a10 = __ldg(p10);
    float4 a11 = __ldg(p11);

    float4 o;
    o.x = c.w00 * a00.x + c.w10 * a10.x + c.w01 * a01.x + c.w11 * a11.x;
    o.y = c.w00 * a00.y + c.w10 * a10.y + c.w01 * a01.y + c.w11 * a11.y;
    o.z = c.w00 * a00.z + c.w10 * a10.z + c.w01 * a01.z + c.w11 * a11.z;
    o.w = c.w00 * a00.w + c.w10 * a10.w + c.w01 * a01.w + c.w11 * a11.w;

    __stcs(reinterpret_cast<float4*>(out + p * C + 4 * k), o);
}

// ---- K0: zero bin counters -------------------------------------------------

__global__ void zero_kernel() {
    if (threadIdx.x < NBINS) g_bin_count[threadIdx.x] = 0;
}

// ---- K1: bin point ids by image row ---------------------------------------

__global__ __launch_bounds__(256)
void bin_kernel(const float2* __restrict__ coords,
                const float* __restrict__ visible,
                float* __restrict__ out,
                int n)
{
    __shared__ int s_cnt[NBINS];
    __shared__ int s_base[NBINS];
    __shared__ int s_rank[NBINS];

    int tid = threadIdx.x;
    if (tid < NBINS) { s_cnt[tid] = 0; s_rank[tid] = 0; }
    __syncthreads();

    int p = blockIdx.x * blockDim.x + tid;
    int bin = -1;
    float2 xy;
    if (p < n) {
        xy = __ldg(coords + p);
        const float m0 = (float)(H - 4);
        float c0 = fmodf(xy.x - 1.0f, m0); if (c0 < 0.0f) c0 += m0; c0 += 1.0f;
        int i0 = (int)floorf(c0);
        bin = i0 >> BIN_SHIFT;
        atomicAdd(&s_cnt[bin], 1);
    }
    __syncthreads();

    if (tid < NBINS)
        s_base[tid] = atomicAdd(&g_bin_count[tid], s_cnt[tid]);
    __syncthreads();

    if (p < n) {
        int r = atomicAdd(&s_rank[bin], 1);
        int slot = s_base[bin] + r;
        if (slot < CAP) {
            g_ids[bin * CAP + slot] = p;
        } else {
            // Overflow fallback (never hit for the benchmark's uniform coords,
            // but keeps the kernel unconditionally correct).
            PointCtx c = make_ctx(xy);
            process_half(c, 0, visible, out, p);
            process_half(c, 1, visible, out, p);
        }
    }
}

// ---- K2: process binned points (locality-ordered) --------------------------

__global__ __launch_bounds__(256)
void process_kernel(const float2* __restrict__ coords,
                    const float* __restrict__ visible,
                    float* __restrict__ out)
{
    int t = blockIdx.x * blockDim.x + threadIdx.x;
    int k   = t & 1;                 // channel half
    int s   = t >> 1;                // slot index across all bins
    int bin = s >> 16;               // s / CAP   (CAP = 65536)
    int idx = s & (CAP - 1);         // s % CAP

    int cnt = min(__ldg(&g_bin_count[bin]), CAP);
    if (idx >= cnt) return;

    int p = __ldg(&g_ids[bin * CAP + idx]);

    // Random 8B gather into the 8MB coord array — L2-hot from K1.
    float2 xy = __ldg(coords + p);
    PointCtx c = make_ctx(xy);
    process_half(c, k, visible, out, p);
}

// ---- launch ---------------------------------------------------------------

extern "C" void kernel_launch(void* const* d_in, const int* in_sizes, int n_in,
                              void* d_out, int out_size)
{
    const float2* coords  = (const float2*)d_in[0];  // [N, 2] fp32
    const float*  visible = (const float*)d_in[1];   // [H, W, C] fp32
    float* out = (float*)d_out;                      // [N, C] fp32

    int n = in_sizes[0] / 2;   // number of points
    (void)n_in; (void)out_size;

    zero_kernel<<<1, 32>>>();

    int threads = 256;
    int bin_blocks = (n + threads - 1) / threads;
    bin_kernel<<<bin_blocks, threads>>>(coords, visible, out, n);

    int total = NBINS * CAP * 2;                    // 2 threads per slot
    int proc_blocks = total / threads;              // 8192
    process_kernel<<<proc_blocks, threads>>>(coords, visible, out);
}